// round 16
// baseline (speedup 1.0000x reference)
#include <cuda_runtime.h>
#include <cuda_bf16.h>
#include <math.h>
#include <stdint.h>

// ---------------- problem dims ----------------
#define NV_   975
#define TT    48
#define T2_   12
#define CC    128
#define VV    3
#define HH    8
#define DD    64
#define HDIM  512
#define LLAY  4
#define NB_   6
#define NHID_ 4
#define DIN_  387
#define NVG   325
#define BNN   650
#define MKV   (BNN*TT)   // 31200
#define MQ    (BNN*T2_)  // 7800
#define LOG2PI_F 1.8378770664093453f

// k-pair counts (multiples of 16)
#define EVKP 208
#define AIKP 192
#define HKP  256

#define NKV  2048  // 32 (l,h) slices x 64

// ---------------- fp32 scratch ----------------
__device__ float g_keys[LLAY*HH*MKV*DD];
__device__ float g_vals[LLAY*HH*MKV*DD];
__device__ float g_attval[MQ*HDIM];
__device__ float g_att[MQ*HDIM];
__device__ float g_s[MQ*VV];
__device__ float g_t[MQ*VV];
__device__ float g_u[MQ*VV];
__device__ float g_ld[MQ*VV];

// ---------------- packed bf16 hi/lo activation planes (A: [M][KP2]) ----------------
__device__ __align__(128) unsigned a_ev_h[MKV*EVKP], a_ev_l[MKV*EVKP];
__device__ __align__(128) unsigned a_ai_h[MQ*AIKP],  a_ai_l[MQ*AIKP];
__device__ __align__(128) unsigned a_av_h[MQ*HKP],   a_av_l[MQ*HKP];
__device__ __align__(128) unsigned a_h1h[MQ*HKP], a_h1l[MQ*HKP];
__device__ __align__(128) unsigned a_h2h[MQ*HKP], a_h2l[MQ*HKP];
__device__ __align__(128) unsigned a_h3h[MQ*HKP], a_h3l[MQ*HKP];
__device__ __align__(128) unsigned a_h4h[MQ*HKP], a_h4l[MQ*HKP];

// ---------------- transposed weight planes (B: [N][KP2], K-major rows) ----------------
__device__ __align__(128) unsigned w_shT_h[HDIM*AIKP], w_shT_l[HDIM*AIKP];
__device__ __align__(128) unsigned w_f1T_h[LLAY*HDIM*HKP], w_f1T_l[LLAY*HDIM*HKP];
__device__ __align__(128) unsigned w_f2T_h[LLAY*HDIM*HKP], w_f2T_l[LLAY*HDIM*HKP];
__device__ __align__(128) unsigned w_inT_h[2*NB_*HDIM*HKP], w_inT_l[2*NB_*HDIM*HKP];
__device__ __align__(128) unsigned w_hdT_h[2*NB_*NHID_*HDIM*HKP], w_hdT_l[2*NB_*NHID_*HDIM*HKP];
__device__ __align__(128) unsigned w_kvT_h[2*NKV*EVKP], w_kvT_l[2*NKV*EVKP];

// ---------------- helpers ----------------
__device__ __forceinline__ unsigned splitpack(float x0, float x1, unsigned& lo) {
    __nv_bfloat16 h0 = __float2bfloat16_rn(x0);
    __nv_bfloat16 h1 = __float2bfloat16_rn(x1);
    float r0 = x0 - __bfloat162float(h0);
    float r1 = x1 - __bfloat162float(h1);
    __nv_bfloat162 hp = __halves2bfloat162(h0, h1);
    __nv_bfloat162 lp = __halves2bfloat162(__float2bfloat16_rn(r0), __float2bfloat16_rn(r1));
    lo = *reinterpret_cast<unsigned*>(&lp);
    return *reinterpret_cast<unsigned*>(&hp);
}

__device__ __forceinline__ void cpa16s(unsigned saddr, const void* gsrc) {
    asm volatile("cp.async.cg.shared.global [%0], [%1], 16;" :: "r"(saddr), "l"(gsrc));
}

__device__ __forceinline__ void mma16(float* c, const unsigned* a, const unsigned* b) {
    asm volatile(
        "mma.sync.aligned.m16n8k16.row.col.f32.bf16.bf16.f32 "
        "{%0,%1,%2,%3}, {%4,%5,%6,%7}, {%8,%9}, {%0,%1,%2,%3};"
        : "+f"(c[0]), "+f"(c[1]), "+f"(c[2]), "+f"(c[3])
        : "r"(a[0]), "r"(a[1]), "r"(a[2]), "r"(a[3]), "r"(b[0]), "r"(b[1]));
}

template <int A> __device__ __forceinline__ float actf(float v) {
    if (A == 1) return fmaxf(v, 0.f);
    if (A == 2) return tanhf(v);
    return v;
}

// ---------------- weight pre-conversion (transposed: src[z][K][N] -> [z][N][KP2]) ----------------
__global__ void k_convwT(const float* __restrict__ src, unsigned* __restrict__ dhi,
                         unsigned* __restrict__ dlo, int K, int N, int KP2, long zstride) {
    long z = blockIdx.z;
    src += z * zstride;
    dhi += z * (long)N * KP2;
    dlo += z * (long)N * KP2;
    int idx = blockIdx.x * 256 + threadIdx.x;
    if (idx >= N * KP2) return;
    int n = idx / KP2, kp = idx - n * KP2;
    float x0 = (2 * kp     < K) ? src[(long)(2 * kp) * N + n]     : 0.f;
    float x1 = (2 * kp + 1 < K) ? src[(long)(2 * kp + 1) * N + n] : 0.f;
    unsigned lo, hi = splitpack(x0, x1, lo);
    dhi[idx] = hi; dlo[idx] = lo;
}

// ---------------- builders ----------------
__global__ void k_build_ev(const float* __restrict__ enc, const float* __restrict__ tv) {
    long idx = (long)blockIdx.x * 256 + threadIdx.x;
    if (idx >= (long)MKV * EVKP) return;
    int kp = (int)(idx % EVKP);
    int m  = (int)(idx / EVKP);
    int b = m / TT, tt = m % TT;
    int ob = b / NVG, nvb = (b % NVG) * VV;
    float x[2];
#pragma unroll
    for (int t = 0; t < 2; t++) {
        int e = 2 * kp + t;
        float v = 0.f;
        if (e < DIN_) {
            int vv = e / (CC + 1), cc = e % (CC + 1);
            int nv = nvb + vv;
            if (cc < CC) v = enc[(((long)ob * NV_ + nv) * TT + tt) * CC + cc];
            else         v = tv[((long)ob * NV_ + nv) * TT + tt];
        }
        x[t] = v;
    }
    unsigned lo, hi = splitpack(x[0], x[1], lo);
    a_ev_h[idx] = hi; a_ev_l[idx] = lo;
}

__global__ void k_build_attin(const float* __restrict__ enc) {
    long idx = (long)blockIdx.x * 256 + threadIdx.x;
    if (idx >= (long)MQ * AIKP) return;
    int kp = (int)(idx % AIKP);
    int m  = (int)(idx / AIKP);
    int b = m / T2_, q = m % T2_;
    int ob = b / NVG, nvb = (b % NVG) * VV;
    float x[2];
#pragma unroll
    for (int t = 0; t < 2; t++) {
        int e = 2 * kp + t;
        int vv = e / CC, cc = e % CC;
        x[t] = enc[(((long)ob * NV_ + nvb + vv) * TT + (TT - T2_) + q) * CC + cc];
    }
    unsigned lo, hi = splitpack(x[0], x[1], lo);
    a_ai_h[idx] = hi; a_ai_l[idx] = lo;
}

// init u/ld, zero g_s/g_t accumulators + out
__global__ void k_init_u(const float* __restrict__ tv, float* __restrict__ out) {
    int m = blockIdx.x * 256 + threadIdx.x;
    if (m >= MQ) return;
    if (m < BNN) out[m] = 0.f;
    int b = m / T2_, q = m % T2_;
    int ob = b / NVG, nvb = (b % NVG) * VV;
#pragma unroll
    for (int v = 0; v < 3; v++) {
        g_u[m * 3 + v]  = tv[((long)ob * NV_ + nvb + v) * TT + (TT - T2_) + q];
        g_ld[m * 3 + v] = 0.f;
        g_s[m * 3 + v]  = 0.f;
        g_t[m * 3 + v]  = 0.f;
    }
}

// coupling + BN stats + BN apply + final-NLL, all per column
__global__ void k_cpl_bn(const float* __restrict__ sb, const float* __restrict__ tb,
                         const float* __restrict__ lgam, const float* __restrict__ beta,
                         float* __restrict__ out, int blk) {
    int col = blockIdx.x;          // 0..35 = t2*3+v
    int v   = col % VV;
    int mask = (v + blk) & 1;
    int tid = threadIdx.x;
    bool last = (blk == NB_ - 1);
    __shared__ float rs[256], rq[256];
    __shared__ float s_mean, s_var;
    float sbv = sb[v], tbv = tb[v];
    float s = 0.f, q = 0.f;
    for (int b = tid; b < BNN; b += 256) {
        int e = b * (T2_ * VV) + col;
        float u = g_u[e];
        if (!mask) {
            float sv = g_s[e] + sbv;
            float tv = g_t[e] + tbv;
            u = (u - tv) * expf(-sv);
            g_u[e] = u;
            g_ld[e] -= sv;
        }
        if (!last) { g_s[e] = 0.f; g_t[e] = 0.f; }
        s += u; q += u * u;
    }
    rs[tid] = s; rq[tid] = q;
    __syncthreads();
    for (int st = 128; st > 0; st >>= 1) {
        if (tid < st) { rs[tid] += rs[tid + st]; rq[tid] += rq[tid + st]; }
        __syncthreads();
    }
    if (tid == 0) {
        float mean = rs[0] / (float)BNN;
        s_mean = mean;
        s_var  = rq[0] / (float)BNN - mean * mean;
    }
    __syncthreads();
    float mean = s_mean, var = s_var;
    float lg = lgam[v], bt = beta[v];
    float sc = expf(lg) * rsqrtf(var + 1e-5f);
    float ldadd = lg - 0.5f * logf(var + 1e-5f);
    for (int b = tid; b < BNN; b += 256) {
        int e = b * (T2_ * VV) + col;
        float u  = sc * (g_u[e] - mean) + bt;
        float ld = g_ld[e] + ldadd;
        if (!last) {
            g_u[e] = u;
            g_ld[e] = ld;
        } else {
            atomicAdd(&out[b], 0.5f * u * u + 0.5f * LOG2PI_F - ld);
        }
    }
}

// ---------------- bf16x3 HMMA GEMM, 128x128 block tile ----------------
#define PITCH 20
#define PLW   (128*PITCH)
#define STW   (4*PLW)
#define GSMEM (2*STW*4)

// CM: 0 = fp32 C row-major; 1 = packed planes Ph/Pl; 2 = KV scatter C[slice][m][64];
//     3 = fused out-layer atomics into C[row*3+v] (wout = out weights);
//     4 = planes output with rank-3 mu epilogue add (wout = W_mu rows [3][512], blk = flow block)
template <int ACT0, int ACT1, int CM>
__global__ void __launch_bounds__(256, 2)
k_mma(const unsigned* __restrict__ Ah0, const unsigned* __restrict__ Al0,
      const unsigned* __restrict__ Wh0, const unsigned* __restrict__ Wl0,
      const float* __restrict__ b0, float* __restrict__ C0,
      unsigned* __restrict__ Ph0, unsigned* __restrict__ Pl0,
      const unsigned* __restrict__ Ah1, const unsigned* __restrict__ Al1,
      const unsigned* __restrict__ Wh1, const unsigned* __restrict__ Wl1,
      const float* __restrict__ b1, float* __restrict__ C1,
      unsigned* __restrict__ Ph1, unsigned* __restrict__ Pl1,
      int M, int N, int KP2,
      const float* __restrict__ wout0, const float* __restrict__ wout1, int blk) {
    extern __shared__ __align__(16) unsigned dsm[];

    bool first = (blockIdx.z == 0);
    const unsigned* Ah = first ? Ah0 : Ah1;
    const unsigned* Al = first ? Al0 : Al1;
    const unsigned* Wh = first ? Wh0 : Wh1;
    const unsigned* Wl = first ? Wl0 : Wl1;
    const float* bias  = first ? b0 : b1;
    float* C           = first ? C0 : C1;
    unsigned* Ph       = first ? Ph0 : Ph1;
    unsigned* Pl       = first ? Pl0 : Pl1;
    const float* wout  = first ? wout0 : wout1;

    int tile_m = blockIdx.y * 128;
    int tile_n = blockIdx.x * 128;
    int tid = threadIdx.x, lane = tid & 31, wid = tid >> 5;
    int grp = lane >> 2, tig = lane & 3;
    int wm = wid & 3, wn = wid >> 2;
    unsigned sbb = (unsigned)__cvta_generic_to_shared(dsm);

    float acc[2][8][4];
#pragma unroll
    for (int i = 0; i < 2; i++)
#pragma unroll
        for (int j = 0; j < 8; j++)
#pragma unroll
            for (int e = 0; e < 4; e++) acc[i][j][e] = 0.f;

    auto load_stage = [&](int st, int kp0) {
        unsigned base = (unsigned)st * STW;
#pragma unroll
        for (int t = 0; t < 4; t++) {
            int idx = tid + t * 256;
            int p = idx >> 9, r = (idx >> 2) & 127, c = idx & 3;
            int gm = tile_m + r; if (gm >= M) gm = M - 1;
            const unsigned* src = (p ? Al : Ah) + (long)gm * KP2 + kp0 + c * 4;
            cpa16s(sbb + (base + (unsigned)p * PLW + (unsigned)(r * PITCH + c * 4)) * 4u, src);
        }
#pragma unroll
        for (int t = 0; t < 4; t++) {
            int idx = tid + t * 256;
            int p = idx >> 9, r = (idx >> 2) & 127, c = idx & 3;
            int gn = tile_n + r;
            const unsigned* src = (p ? Wl : Wh) + (long)gn * KP2 + kp0 + c * 4;
            cpa16s(sbb + (base + 2u * PLW + (unsigned)p * PLW + (unsigned)(r * PITCH + c * 4)) * 4u, src);
        }
        asm volatile("cp.async.commit_group;" ::: "memory");
    };

    int iters = KP2 / 16;
    load_stage(0, 0);

    for (int it = 0; it < iters; it++) {
        if (it + 1 < iters) {
            load_stage((it + 1) & 1, (it + 1) * 16);
            asm volatile("cp.async.wait_group 1;" ::: "memory");
        } else {
            asm volatile("cp.async.wait_group 0;" ::: "memory");
        }
        __syncthreads();

        unsigned base = (unsigned)(it & 1) * STW;
        const unsigned* SAh = dsm + base;
        const unsigned* SAl = dsm + base + PLW;
        const unsigned* SBh = dsm + base + 2 * PLW;
        const unsigned* SBl = dsm + base + 3 * PLW;

#pragma unroll
        for (int s2 = 0; s2 < 2; s2++) {
            int kb = s2 * 8;
            unsigned ah[2][4], al[2][4];
#pragma unroll
            for (int i = 0; i < 2; i++) {
                int rb = wm * 32 + i * 16 + grp;
                ah[i][0] = SAh[rb * PITCH + kb + tig];
                ah[i][1] = SAh[(rb + 8) * PITCH + kb + tig];
                ah[i][2] = SAh[rb * PITCH + kb + tig + 4];
                ah[i][3] = SAh[(rb + 8) * PITCH + kb + tig + 4];
                al[i][0] = SAl[rb * PITCH + kb + tig];
                al[i][1] = SAl[(rb + 8) * PITCH + kb + tig];
                al[i][2] = SAl[rb * PITCH + kb + tig + 4];
                al[i][3] = SAl[(rb + 8) * PITCH + kb + tig + 4];
            }
#pragma unroll
            for (int j = 0; j < 8; j++) {
                int nb = wn * 64 + j * 8 + grp;
                unsigned bh[2], bl[2];
                bh[0] = SBh[nb * PITCH + kb + tig];
                bh[1] = SBh[nb * PITCH + kb + tig + 4];
                bl[0] = SBl[nb * PITCH + kb + tig];
                bl[1] = SBl[nb * PITCH + kb + tig + 4];
#pragma unroll
                for (int i = 0; i < 2; i++) {
                    mma16(acc[i][j], ah[i], bh);
                    mma16(acc[i][j], al[i], bh);
                    mma16(acc[i][j], ah[i], bl);
                }
            }
        }
        __syncthreads();
    }

    int np2 = N >> 1;
    float part[2][2][3];
    if (CM == 3) {
#pragma unroll
        for (int i = 0; i < 2; i++)
#pragma unroll
            for (int rp = 0; rp < 2; rp++)
#pragma unroll
                for (int v = 0; v < 3; v++) part[i][rp][v] = 0.f;
    }
#pragma unroll
    for (int i = 0; i < 2; i++) {
        int row0 = tile_m + wm * 32 + i * 16 + grp;
        int row1 = row0 + 8;
        float mu0[3], mu1[3];
        if (CM == 4) {
            int r0 = (row0 < M) ? row0 : M - 1;
            int r1 = (row1 < M) ? row1 : M - 1;
#pragma unroll
            for (int v = 0; v < 3; v++) {
                float mk = ((v + blk) & 1) ? 1.f : 0.f;
                mu0[v] = mk * g_u[r0 * 3 + v];
                mu1[v] = mk * g_u[r1 * 3 + v];
            }
        }
#pragma unroll
        for (int j = 0; j < 8; j++) {
            int col = tile_n + wn * 64 + j * 8 + tig * 2;
            float b0v = bias[col], b1v = bias[col + 1];
            float v00 = acc[i][j][0] + b0v, v01 = acc[i][j][1] + b1v;
            float v10 = acc[i][j][2] + b0v, v11 = acc[i][j][3] + b1v;
            if (CM == 4) {
                float w00 = wout[col],        w01 = wout[col + 1];
                float w10 = wout[HDIM + col], w11 = wout[HDIM + col + 1];
                float w20 = wout[2*HDIM + col], w21 = wout[2*HDIM + col + 1];
                v00 += mu0[0]*w00 + mu0[1]*w10 + mu0[2]*w20;
                v01 += mu0[0]*w01 + mu0[1]*w11 + mu0[2]*w21;
                v10 += mu1[0]*w00 + mu1[1]*w10 + mu1[2]*w20;
                v11 += mu1[0]*w01 + mu1[1]*w11 + mu1[2]*w21;
            }
            if (first) {
                v00 = actf<ACT0>(v00); v01 = actf<ACT0>(v01);
                v10 = actf<ACT0>(v10); v11 = actf<ACT0>(v11);
            } else {
                v00 = actf<ACT1>(v00); v01 = actf<ACT1>(v01);
                v10 = actf<ACT1>(v10); v11 = actf<ACT1>(v11);
            }
            if (CM == 3) {
#pragma unroll
                for (int v = 0; v < 3; v++) {
                    float w0 = wout[col * 3 + v], w1 = wout[(col + 1) * 3 + v];
                    part[i][0][v] += v00 * w0 + v01 * w1;
                    part[i][1][v] += v10 * w0 + v11 * w1;
                }
            } else if (CM == 2) {
                int slice = col >> 6, cis = col & 63;
                float* d0 = C + ((long)slice * M + row0) * 64 + cis;
                float* d1 = C + ((long)slice * M + row1) * 64 + cis;
                if (row0 < M) { d0[0] = v00; d0[1] = v01; }
                if (row1 < M) { d1[0] = v10; d1[1] = v11; }
            } else if (CM == 0) {
                if (row0 < M) { C[(long)row0 * N + col] = v00; C[(long)row0 * N + col + 1] = v01; }
                if (row1 < M) { C[(long)row1 * N + col] = v10; C[(long)row1 * N + col + 1] = v11; }
            } else {
                unsigned lo, hi;
                if (row0 < M) {
                    hi = splitpack(v00, v01, lo);
                    Ph[(long)row0 * np2 + (col >> 1)] = hi;
                    Pl[(long)row0 * np2 + (col >> 1)] = lo;
                }
                if (row1 < M) {
                    hi = splitpack(v10, v11, lo);
                    Ph[(long)row1 * np2 + (col >> 1)] = hi;
                    Pl[(long)row1 * np2 + (col >> 1)] = lo;
                }
            }
        }
    }
    if (CM == 3) {
#pragma unroll
        for (int i = 0; i < 2; i++) {
            int row0 = tile_m + wm * 32 + i * 16 + grp;
            int row1 = row0 + 8;
#pragma unroll
            for (int v = 0; v < 3; v++) {
                if (row0 < M) atomicAdd(&C[row0 * 3 + v], part[i][0][v]);
                if (row1 < M) atomicAdd(&C[row1 * 3 + v], part[i][1][v]);
            }
        }
    }
}

// ---------------- attention ----------------
__global__ void k_attn2(const float* __restrict__ keys, const float* __restrict__ vals, int l) {
    int h = blockIdx.x & 7, b = blockIdx.x >> 3;
    int tid = threadIdx.x, lane = tid & 31, wq = tid >> 5;
    __shared__ float KsT[DD * TT];
    __shared__ float Vs[TT * DD];
    __shared__ float Qs[T2_ * DD];
    __shared__ float Ps[4][64];

    long base = ((long)(l * HH + h) * MKV + (long)b * TT) * DD;
    const float4* k4 = (const float4*)(keys + base);
    const float4* v4 = (const float4*)(vals + base);
    for (int i = tid; i < TT * DD / 4; i += 128) {
        float4 kv = k4[i];
        int w = i >> 4, d = (i & 15) << 2;
        KsT[(d + 0) * TT + w] = kv.x;
        KsT[(d + 1) * TT + w] = kv.y;
        KsT[(d + 2) * TT + w] = kv.z;
        KsT[(d + 3) * TT + w] = kv.w;
        ((float4*)Vs)[i] = v4[i];
    }
    for (int i = tid; i < T2_ * DD / 4; i += 128) {
        int q = i >> 4, d4 = (i & 15);
        ((float4*)Qs)[i] = *(const float4*)(g_attval + (long)(b * T2_ + q) * HDIM + h * DD + d4 * 4);
    }
    __syncthreads();

#pragma unroll
    for (int qi = 0; qi < 3; qi++) {
        int q = wq + qi * 4;
        int lim = (TT - T2_) + q;
        float d0 = 0.f, d1 = 0.f;
        const float* qrow = Qs + q * DD;
#pragma unroll
        for (int d = 0; d < DD; d++) {
            float qd = qrow[d];
            d0 += qd * KsT[d * TT + lane];
            d1 += qd * KsT[d * TT + ((lane + 32) & 63)];
        }
        float s0 = (lane < lim) ? d0 * 0.125f : -1e30f;
        float s1 = (lane + 32 < lim) ? d1 * 0.125f : -1e30f;
        float mx = fmaxf(s0, s1);
#pragma unroll
        for (int o = 16; o; o >>= 1) mx = fmaxf(mx, __shfl_xor_sync(0xffffffffu, mx, o));
        float e0 = (lane < lim) ? expf(s0 - mx) : 0.f;
        float e1 = (lane + 32 < lim) ? expf(s1 - mx) : 0.f;
        float sm = e0 + e1;
#pragma unroll
        for (int o = 16; o; o >>= 1) sm += __shfl_xor_sync(0xffffffffu, sm, o);
        Ps[wq][lane] = e0;
        Ps[wq][lane + 32] = e1;
        __syncwarp();
        float inv = 1.f / sm;
        float o0 = 0.f, o1 = 0.f;
        for (int w2 = 0; w2 < lim; w2++) {
            float p = Ps[wq][w2];
            o0 += p * Vs[w2 * DD + lane];
            o1 += p * Vs[w2 * DD + lane + 32];
        }
        long orow = (long)(b * T2_ + q) * HDIM + h * DD;
        g_att[orow + lane] = o0 * inv;
        g_att[orow + lane + 32] = o1 * inv;
        __syncwarp();
    }
}

// ---------------- add + layernorm: warp per row, shuffle reductions ----------------
__global__ void k_add_ln(float* __restrict__ x, const float* __restrict__ y,
                         const float* __restrict__ gamma, const float* __restrict__ beta) {
    int w = threadIdx.x >> 5, lane = threadIdx.x & 31;
    int m = blockIdx.x * 8 + w;
    long base = (long)m * HDIM;
    float4 xv[4];
#pragma unroll
    for (int k = 0; k < 4; k++) {
        int off = k * 128 + lane * 4;
        float4 a = *(const float4*)&x[base + off];
        float4 b = *(const float4*)&y[base + off];
        xv[k].x = a.x + b.x; xv[k].y = a.y + b.y;
        xv[k].z = a.z + b.z; xv[k].w = a.w + b.w;
    }
    float s = 0.f;
#pragma unroll
    for (int k = 0; k < 4; k++) s += xv[k].x + xv[k].y + xv[k].z + xv[k].w;
#pragma unroll
    for (int o = 16; o; o >>= 1) s += __shfl_xor_sync(0xffffffffu, s, o);
    float mean = s / (float)HDIM;
    float q = 0.f;
#pragma unroll
    for (int k = 0; k < 4; k++) {
        xv[k].x -= mean; xv[k].y -= mean; xv[k].z -= mean; xv[k].w -= mean;
        q += xv[k].x * xv[k].x + xv[k].y * xv[k].y + xv[k].z * xv[k].z + xv[k].w * xv[k].w;
    }
#pragma unroll
    for (int o = 16; o; o >>= 1) q += __shfl_xor_sync(0xffffffffu, q, o);
    float r = rsqrtf(q / (float)HDIM + 1e-5f);
#pragma unroll
    for (int k = 0; k < 4; k++) {
        int off = k * 128 + lane * 4;
        float4 g = *(const float4*)&gamma[off];
        float4 bb = *(const float4*)&beta[off];
        float4 o4;
        o4.x = xv[k].x * r * g.x + bb.x;
        o4.y = xv[k].y * r * g.y + bb.y;
        o4.z = xv[k].z * r * g.z + bb.z;
        o4.w = xv[k].w * r * g.w + bb.w;
        *(float4*)&x[base + off] = o4;
        unsigned lo0, hi0 = splitpack(o4.x, o4.y, lo0);
        unsigned lo1, hi1 = splitpack(o4.z, o4.w, lo1);
        long pb = (long)m * HKP + k * 64 + lane * 2;
        a_av_h[pb] = hi0; a_av_h[pb + 1] = hi1;
        a_av_l[pb] = lo0; a_av_l[pb + 1] = lo1;
    }
}

// ---------------- host ----------------
static inline int ceildiv(int a, int b) { return (a + b - 1) / b; }

extern "C" void kernel_launch(void* const* d_in, const int* in_sizes, int n_in,
                              void* d_out, int out_size) {
    const float* encoded   = (const float*)d_in[0];
    const float* true_val  = (const float*)d_in[1];
    const float* W_shift   = (const float*)d_in[2];
    const float* b_shift   = (const float*)d_in[3];
    const float* W_key     = (const float*)d_in[4];
    const float* b_key     = (const float*)d_in[5];
    const float* W_val     = (const float*)d_in[6];
    const float* b_val     = (const float*)d_in[7];
    const float* ln1_s     = (const float*)d_in[8];
    const float* ln1_b     = (const float*)d_in[9];
    const float* ff_w1     = (const float*)d_in[10];
    const float* ff_b1     = (const float*)d_in[11];
    const float* ff_w2     = (const float*)d_in[12];
    const float* ff_b2     = (const float*)d_in[13];
    const float* ln2_s     = (const float*)d_in[14];
    const float* ln2_b     = (const float*)d_in[15];
    const float* s_w_in    = (const float*)d_in[16];
    const float* s_b_in    = (const float*)d_in[17];
    const float* s_w_hid   = (const float*)d_in[18];
    const float* s_b_hid   = (const float*)d_in[19];
    const float* s_w_out   = (const float*)d_in[20];
    const float* s_b_out   = (const float*)d_in[21];
    const float* t_w_in    = (const float*)d_in[22];
    const float* t_b_in    = (const float*)d_in[23];
    const float* t_w_hid   = (const float*)d_in[24];
    const float* t_b_hid   = (const float*)d_in[25];
    const float* t_w_out   = (const float*)d_in[26];
    const float* t_b_out   = (const float*)d_in[27];
    const float* bn_lg     = (const float*)d_in[28];
    const float* bn_bt     = (const float*)d_in[29];

    float *keys, *vals, *attval, *att, *sbuf, *tbuf;
    unsigned *evh, *evl, *aih, *ail, *avh, *avl;
    unsigned *h1h, *h1l, *h2h, *h2l, *h3h, *h3l, *h4h, *h4l;
    unsigned *wshh, *wshl, *wf1h, *wf1l, *wf2h, *wf2l, *winh, *winl, *whdh, *whdl, *wkvh, *wkvl;
    cudaGetSymbolAddress((void**)&keys,   g_keys);
    cudaGetSymbolAddress((void**)&vals,   g_vals);
    cudaGetSymbolAddress((void**)&attval, g_attval);
    cudaGetSymbolAddress((void**)&att,    g_att);
    cudaGetSymbolAddress((void**)&sbuf,   g_s);
    cudaGetSymbolAddress((void**)&tbuf,   g_t);
    cudaGetSymbolAddress((void**)&evh, a_ev_h);  cudaGetSymbolAddress((void**)&evl, a_ev_l);
    cudaGetSymbolAddress((void**)&aih, a_ai_h);  cudaGetSymbolAddress((void**)&ail, a_ai_l);
    cudaGetSymbolAddress((void**)&avh, a_av_h);  cudaGetSymbolAddress((void**)&avl, a_av_l);
    cudaGetSymbolAddress((void**)&h1h, a_h1h);   cudaGetSymbolAddress((void**)&h1l, a_h1l);
    cudaGetSymbolAddress((void**)&h2h, a_h2h);   cudaGetSymbolAddress((void**)&h2l, a_h2l);
    cudaGetSymbolAddress((void**)&h3h, a_h3h);   cudaGetSymbolAddress((void**)&h3l, a_h3l);
    cudaGetSymbolAddress((void**)&h4h, a_h4h);   cudaGetSymbolAddress((void**)&h4l, a_h4l);
    cudaGetSymbolAddress((void**)&wshh, w_shT_h); cudaGetSymbolAddress((void**)&wshl, w_shT_l);
    cudaGetSymbolAddress((void**)&wf1h, w_f1T_h); cudaGetSymbolAddress((void**)&wf1l, w_f1T_l);
    cudaGetSymbolAddress((void**)&wf2h, w_f2T_h); cudaGetSymbolAddress((void**)&wf2l, w_f2T_l);
    cudaGetSymbolAddress((void**)&winh, w_inT_h); cudaGetSymbolAddress((void**)&winl, w_inT_l);
    cudaGetSymbolAddress((void**)&whdh, w_hdT_h); cudaGetSymbolAddress((void**)&whdl, w_hdT_l);
    cudaGetSymbolAddress((void**)&wkvh, w_kvT_h); cudaGetSymbolAddress((void**)&wkvl, w_kvT_l);

    cudaFuncSetAttribute(k_mma<0,0,0>, cudaFuncAttributeMaxDynamicSharedMemorySize, GSMEM);
    cudaFuncSetAttribute(k_mma<0,0,2>, cudaFuncAttributeMaxDynamicSharedMemorySize, GSMEM);
    cudaFuncSetAttribute(k_mma<1,1,1>, cudaFuncAttributeMaxDynamicSharedMemorySize, GSMEM);
    cudaFuncSetAttribute(k_mma<0,0,1>, cudaFuncAttributeMaxDynamicSharedMemorySize, GSMEM);
    cudaFuncSetAttribute(k_mma<2,1,1>, cudaFuncAttributeMaxDynamicSharedMemorySize, GSMEM);
    cudaFuncSetAttribute(k_mma<2,1,3>, cudaFuncAttributeMaxDynamicSharedMemorySize, GSMEM);
    cudaFuncSetAttribute(k_mma<2,1,4>, cudaFuncAttributeMaxDynamicSharedMemorySize, GSMEM);

    long kvoff = (long)NKV * EVKP;
    long inoff = (long)NB_ * HDIM * HKP;
    long hdoff = (long)NB_ * NHID_ * HDIM * HKP;
    long instride = (long)(HDIM + VV) * HDIM;

    // ---- serial prologue: KV convs + builders, KV GEMM at launch #5 ----
    k_convwT<<<dim3(ceildiv(DD*EVKP,256),1,LLAY*HH), 256>>>(W_key, wkvh, wkvl, DIN_, DD, EVKP, (long)DIN_*DD);   // 0
    k_convwT<<<dim3(ceildiv(DD*EVKP,256),1,LLAY*HH), 256>>>(W_val, wkvh+kvoff, wkvl+kvoff, DIN_, DD, EVKP, (long)DIN_*DD); // 1
    k_build_ev<<<(int)(((long)MKV*EVKP + 255)/256), 256>>>(encoded, true_val);                                   // 2
    k_build_attin<<<(int)(((long)MQ*AIKP + 255)/256), 256>>>(encoded);                                           // 3
    k_init_u<<<ceildiv(MQ, 256), 256>>>(true_val, (float*)d_out);                                                // 4

    {
        dim3 g(NKV/128, ceildiv(MKV, 128), 2);
        k_mma<0,0,2><<<g, 256, GSMEM>>>(evh, evl, wkvh, wkvl, b_key, keys, 0, 0,
                                        evh, evl, wkvh+kvoff, wkvl+kvoff, b_val, vals, 0, 0,
                                        MKV, NKV, EVKP, 0, 0, 0);                                                // 5
    }

    // ---- remaining weight conversions (serial) ----
    k_convwT<<<dim3(ceildiv(HDIM*AIKP,256),1,1), 256>>>(W_shift, wshh, wshl, VV*CC, HDIM, AIKP, (long)VV*CC*HDIM);
    k_convwT<<<dim3(ceildiv(HDIM*HKP,256),1,LLAY), 256>>>(ff_w1, wf1h, wf1l, HDIM, HDIM, HKP, (long)HDIM*HDIM);
    k_convwT<<<dim3(ceildiv(HDIM*HKP,256),1,LLAY), 256>>>(ff_w2, wf2h, wf2l, HDIM, HDIM, HKP, (long)HDIM*HDIM);
    k_convwT<<<dim3(ceildiv(HDIM*HKP,256),1,NB_), 256>>>(s_w_in, winh, winl, HDIM, HDIM, HKP, instride);
    k_convwT<<<dim3(ceildiv(HDIM*HKP,256),1,NB_), 256>>>(t_w_in, winh+inoff, winl+inoff, HDIM, HDIM, HKP, instride);
    k_convwT<<<dim3(ceildiv(HDIM*HKP,256),1,NB_*NHID_), 256>>>(s_w_hid, whdh, whdl, HDIM, HDIM, HKP, (long)HDIM*HDIM);
    k_convwT<<<dim3(ceildiv(HDIM*HKP,256),1,NB_*NHID_), 256>>>(t_w_hid, whdh+hdoff, whdl+hdoff, HDIM, HDIM, HKP, (long)HDIM*HDIM);

    // ---- shift ----
    {
        dim3 g(HDIM/128, ceildiv(MQ, 128), 1);
        k_mma<0,0,0><<<g, 256, GSMEM>>>(aih, ail, wshh, wshl, b_shift, attval, 0, 0,
                                        aih, ail, wshh, wshl, b_shift, attval, 0, 0,
                                        MQ, HDIM, AIKP, 0, 0, 0);
    }

    // ---- transformer layers ----
    for (int l = 0; l < LLAY; l++) {
        k_attn2<<<BNN*HH, 128>>>(keys, vals, l);
        k_add_ln<<<MQ/8, 256>>>(attval, att, ln1_s + (long)l*HDIM, ln1_b + (long)l*HDIM);
        dim3 g(HDIM/128, ceildiv(MQ, 128), 1);
        k_mma<1,1,1><<<g, 256, GSMEM>>>(avh, avl, wf1h + (long)l*HDIM*HKP, wf1l + (long)l*HDIM*HKP,
                                        ff_b1 + (long)l*HDIM, 0, h1h, h1l,
                                        avh, avl, wf1h + (long)l*HDIM*HKP, wf1l + (long)l*HDIM*HKP,
                                        ff_b1 + (long)l*HDIM, 0, h1h, h1l,
                                        MQ, HDIM, HKP, 0, 0, 0);
        k_mma<0,0,0><<<g, 256, GSMEM>>>(h1h, h1l, wf2h + (long)l*HDIM*HKP, wf2l + (long)l*HDIM*HKP,
                                        ff_b2 + (long)l*HDIM, att, 0, 0,
                                        h1h, h1l, wf2h + (long)l*HDIM*HKP, wf2l + (long)l*HDIM*HKP,
                                        ff_b2 + (long)l*HDIM, att, 0, 0,
                                        MQ, HDIM, HKP, 0, 0, 0);
        k_add_ln<<<MQ/8, 256>>>(attval, att, ln2_s + (long)l*HDIM, ln2_b + (long)l*HDIM);
    }

    // ---- RealNVP flow: s/t fused into single z=2 launches ----
    dim3 gd(HDIM/128, ceildiv(MQ, 128), 2);

    for (int blk = 0; blk < NB_; blk++) {
        const float* smuw = s_w_in + (long)blk * instride + (long)HDIM * HDIM;
        const float* tmuw = t_w_in + (long)blk * instride + (long)HDIM * HDIM;

        // in-layer: z=0 -> s (tanh -> h1), z=1 -> t (relu -> h3); rank-3 mu epilogue
        k_mma<2,1,4><<<gd, 256, GSMEM>>>(avh, avl, winh + (long)blk*HDIM*HKP, winl + (long)blk*HDIM*HKP,
                                         s_b_in + (long)blk*HDIM, 0, h1h, h1l,
                                         avh, avl, winh + inoff + (long)blk*HDIM*HKP, winl + inoff + (long)blk*HDIM*HKP,
                                         t_b_in + (long)blk*HDIM, 0, h3h, h3l,
                                         MQ, HDIM, HKP, smuw, tmuw, blk);

        unsigned *csh = h1h, *csl = h1l, *nsh = h2h, *nsl = h2l;
        unsigned *cth = h3h, *ctl = h3l, *nth = h4h, *ntl = h4l;
        for (int i = 0; i < NHID_ - 1; i++) {
            long wo = ((long)blk*NHID_ + i)*HDIM*HKP;
            k_mma<2,1,1><<<gd, 256, GSMEM>>>(csh, csl, whdh + wo, whdl + wo,
                                             s_b_hid + ((long)blk*NHID_ + i)*HDIM, 0, nsh, nsl,
                                             cth, ctl, whdh + hdoff + wo, whdl + hdoff + wo,
                                             t_b_hid + ((long)blk*NHID_ + i)*HDIM, 0, nth, ntl,
                                             MQ, HDIM, HKP, 0, 0, 0);
            unsigned* t;
            t = csh; csh = nsh; nsh = t;  t = csl; csl = nsl; nsl = t;
            t = cth; cth = nth; nth = t;  t = ctl; ctl = ntl; ntl = t;
        }
        // last hidden GEMM: fused out-layer accumulation into g_s / g_t
        {
            int i = NHID_ - 1;
            long wo = ((long)blk*NHID_ + i)*HDIM*HKP;
            k_mma<2,1,3><<<gd, 256, GSMEM>>>(csh, csl, whdh + wo, whdl + wo,
                                             s_b_hid + ((long)blk*NHID_ + i)*HDIM, sbuf, 0, 0,
                                             cth, ctl, whdh + hdoff + wo, whdl + hdoff + wo,
                                             t_b_hid + ((long)blk*NHID_ + i)*HDIM, tbuf, 0, 0,
                                             MQ, HDIM, HKP,
                                             s_w_out + (long)blk*HDIM*VV, t_w_out + (long)blk*HDIM*VV, 0);
        }

        // fused coupling + BN stats + BN apply + final-NLL
        k_cpl_bn<<<T2_*VV, 256>>>(s_b_out + (long)blk*VV, t_b_out + (long)blk*VV,
                                  bn_lg + (long)blk*VV, bn_bt + (long)blk*VV,
                                  (float*)d_out, blk);
    }
}

// round 17
// speedup vs baseline: 1.1166x; 1.1166x over previous
#include <cuda_runtime.h>
#include <cuda_bf16.h>
#include <math.h>
#include <stdint.h>

// ---------------- problem dims ----------------
#define NV_   975
#define TT    48
#define T2_   12
#define CC    128
#define VV    3
#define HH    8
#define DD    64
#define HDIM  512
#define LLAY  4
#define NB_   6
#define NHID_ 4
#define DIN_  387
#define NVG   325
#define BNN   650
#define MKV   (BNN*TT)   // 31200
#define MQ    (BNN*T2_)  // 7800
#define LOG2PI_F 1.8378770664093453f

// k-pair counts (multiples of 16)
#define EVKP 208
#define AIKP 192
#define HKP  256

#define NKV  2048  // 32 (l,h) slices x 64

// ---------------- fp32 scratch ----------------
__device__ float g_keys[LLAY*HH*MKV*DD];
__device__ float g_vals[LLAY*HH*MKV*DD];
__device__ float g_attval[MQ*HDIM];
__device__ float g_att[MQ*HDIM];
__device__ float g_s[MQ*VV];
__device__ float g_t[MQ*VV];
__device__ float g_u[MQ*VV];
__device__ float g_ld[MQ*VV];

// ---------------- packed bf16 hi/lo activation planes (A: [M][KP2]) ----------------
__device__ __align__(128) unsigned a_ev_h[MKV*EVKP], a_ev_l[MKV*EVKP];
__device__ __align__(128) unsigned a_ai_h[MQ*AIKP],  a_ai_l[MQ*AIKP];
__device__ __align__(128) unsigned a_av_h[MQ*HKP],   a_av_l[MQ*HKP];
__device__ __align__(128) unsigned a_h1h[MQ*HKP], a_h1l[MQ*HKP];
__device__ __align__(128) unsigned a_h2h[MQ*HKP], a_h2l[MQ*HKP];
__device__ __align__(128) unsigned a_h3h[MQ*HKP], a_h3l[MQ*HKP];
__device__ __align__(128) unsigned a_h4h[MQ*HKP], a_h4l[MQ*HKP];

// ---------------- transposed weight planes (B: [N][KP2], K-major rows) ----------------
__device__ __align__(128) unsigned w_shT_h[HDIM*AIKP], w_shT_l[HDIM*AIKP];
__device__ __align__(128) unsigned w_f1T_h[LLAY*HDIM*HKP], w_f1T_l[LLAY*HDIM*HKP];
__device__ __align__(128) unsigned w_f2T_h[LLAY*HDIM*HKP], w_f2T_l[LLAY*HDIM*HKP];
__device__ __align__(128) unsigned w_inT_h[2*NB_*HDIM*HKP], w_inT_l[2*NB_*HDIM*HKP];
__device__ __align__(128) unsigned w_hdT_h[2*NB_*NHID_*HDIM*HKP], w_hdT_l[2*NB_*NHID_*HDIM*HKP];
__device__ __align__(128) unsigned w_kvT_h[2*NKV*EVKP], w_kvT_l[2*NKV*EVKP];

// ---------------- helpers ----------------
__device__ __forceinline__ unsigned splitpack(float x0, float x1, unsigned& lo) {
    __nv_bfloat16 h0 = __float2bfloat16_rn(x0);
    __nv_bfloat16 h1 = __float2bfloat16_rn(x1);
    float r0 = x0 - __bfloat162float(h0);
    float r1 = x1 - __bfloat162float(h1);
    __nv_bfloat162 hp = __halves2bfloat162(h0, h1);
    __nv_bfloat162 lp = __halves2bfloat162(__float2bfloat16_rn(r0), __float2bfloat16_rn(r1));
    lo = *reinterpret_cast<unsigned*>(&lp);
    return *reinterpret_cast<unsigned*>(&hp);
}

__device__ __forceinline__ void cpa16s(unsigned saddr, const void* gsrc) {
    asm volatile("cp.async.cg.shared.global [%0], [%1], 16;" :: "r"(saddr), "l"(gsrc));
}

__device__ __forceinline__ void mma16(float* c, const unsigned* a, const unsigned* b) {
    asm volatile(
        "mma.sync.aligned.m16n8k16.row.col.f32.bf16.bf16.f32 "
        "{%0,%1,%2,%3}, {%4,%5,%6,%7}, {%8,%9}, {%0,%1,%2,%3};"
        : "+f"(c[0]), "+f"(c[1]), "+f"(c[2]), "+f"(c[3])
        : "r"(a[0]), "r"(a[1]), "r"(a[2]), "r"(a[3]), "r"(b[0]), "r"(b[1]));
}

template <int A> __device__ __forceinline__ float actf(float v) {
    if (A == 1) return fmaxf(v, 0.f);
    if (A == 2) return tanhf(v);
    return v;
}

// ---------------- weight pre-conversion (transposed: src[z][K][N] -> [z][N][KP2]) ----------------
__global__ void k_convwT(const float* __restrict__ src, unsigned* __restrict__ dhi,
                         unsigned* __restrict__ dlo, int K, int N, int KP2, long zstride) {
    long z = blockIdx.z;
    src += z * zstride;
    dhi += z * (long)N * KP2;
    dlo += z * (long)N * KP2;
    int idx = blockIdx.x * 256 + threadIdx.x;
    if (idx >= N * KP2) return;
    int n = idx / KP2, kp = idx - n * KP2;
    float x0 = (2 * kp     < K) ? src[(long)(2 * kp) * N + n]     : 0.f;
    float x1 = (2 * kp + 1 < K) ? src[(long)(2 * kp + 1) * N + n] : 0.f;
    unsigned lo, hi = splitpack(x0, x1, lo);
    dhi[idx] = hi; dlo[idx] = lo;
}

// ---------------- builders ----------------
__global__ void k_build_ev(const float* __restrict__ enc, const float* __restrict__ tv) {
    long idx = (long)blockIdx.x * 256 + threadIdx.x;
    if (idx >= (long)MKV * EVKP) return;
    int kp = (int)(idx % EVKP);
    int m  = (int)(idx / EVKP);
    int b = m / TT, tt = m % TT;
    int ob = b / NVG, nvb = (b % NVG) * VV;
    float x[2];
#pragma unroll
    for (int t = 0; t < 2; t++) {
        int e = 2 * kp + t;
        float v = 0.f;
        if (e < DIN_) {
            int vv = e / (CC + 1), cc = e % (CC + 1);
            int nv = nvb + vv;
            if (cc < CC) v = enc[(((long)ob * NV_ + nv) * TT + tt) * CC + cc];
            else         v = tv[((long)ob * NV_ + nv) * TT + tt];
        }
        x[t] = v;
    }
    unsigned lo, hi = splitpack(x[0], x[1], lo);
    a_ev_h[idx] = hi; a_ev_l[idx] = lo;
}

__global__ void k_build_attin(const float* __restrict__ enc) {
    long idx = (long)blockIdx.x * 256 + threadIdx.x;
    if (idx >= (long)MQ * AIKP) return;
    int kp = (int)(idx % AIKP);
    int m  = (int)(idx / AIKP);
    int b = m / T2_, q = m % T2_;
    int ob = b / NVG, nvb = (b % NVG) * VV;
    float x[2];
#pragma unroll
    for (int t = 0; t < 2; t++) {
        int e = 2 * kp + t;
        int vv = e / CC, cc = e % CC;
        x[t] = enc[(((long)ob * NV_ + nvb + vv) * TT + (TT - T2_) + q) * CC + cc];
    }
    unsigned lo, hi = splitpack(x[0], x[1], lo);
    a_ai_h[idx] = hi; a_ai_l[idx] = lo;
}

// init u/ld, zero g_s/g_t accumulators + out
__global__ void k_init_u(const float* __restrict__ tv, float* __restrict__ out) {
    int m = blockIdx.x * 256 + threadIdx.x;
    if (m >= MQ) return;
    if (m < BNN) out[m] = 0.f;
    int b = m / T2_, q = m % T2_;
    int ob = b / NVG, nvb = (b % NVG) * VV;
#pragma unroll
    for (int v = 0; v < 3; v++) {
        g_u[m * 3 + v]  = tv[((long)ob * NV_ + nvb + v) * TT + (TT - T2_) + q];
        g_ld[m * 3 + v] = 0.f;
        g_s[m * 3 + v]  = 0.f;
        g_t[m * 3 + v]  = 0.f;
    }
}

// coupling + BN stats + BN apply + final-NLL, all per column
__global__ void k_cpl_bn(const float* __restrict__ sb, const float* __restrict__ tb,
                         const float* __restrict__ lgam, const float* __restrict__ beta,
                         float* __restrict__ out, int blk) {
    int col = blockIdx.x;          // 0..35 = t2*3+v
    int v   = col % VV;
    int mask = (v + blk) & 1;
    int tid = threadIdx.x;
    bool last = (blk == NB_ - 1);
    __shared__ float rs[256], rq[256];
    __shared__ float s_mean, s_var;
    float sbv = sb[v], tbv = tb[v];
    float s = 0.f, q = 0.f;
    for (int b = tid; b < BNN; b += 256) {
        int e = b * (T2_ * VV) + col;
        float u = g_u[e];
        if (!mask) {
            float sv = g_s[e] + sbv;
            float tv = g_t[e] + tbv;
            u = (u - tv) * expf(-sv);
            g_u[e] = u;
            g_ld[e] -= sv;
        }
        if (!last) { g_s[e] = 0.f; g_t[e] = 0.f; }
        s += u; q += u * u;
    }
    rs[tid] = s; rq[tid] = q;
    __syncthreads();
    for (int st = 128; st > 0; st >>= 1) {
        if (tid < st) { rs[tid] += rs[tid + st]; rq[tid] += rq[tid + st]; }
        __syncthreads();
    }
    if (tid == 0) {
        float mean = rs[0] / (float)BNN;
        s_mean = mean;
        s_var  = rq[0] / (float)BNN - mean * mean;
    }
    __syncthreads();
    float mean = s_mean, var = s_var;
    float lg = lgam[v], bt = beta[v];
    float sc = expf(lg) * rsqrtf(var + 1e-5f);
    float ldadd = lg - 0.5f * logf(var + 1e-5f);
    for (int b = tid; b < BNN; b += 256) {
        int e = b * (T2_ * VV) + col;
        float u  = sc * (g_u[e] - mean) + bt;
        float ld = g_ld[e] + ldadd;
        if (!last) {
            g_u[e] = u;
            g_ld[e] = ld;
        } else {
            atomicAdd(&out[b], 0.5f * u * u + 0.5f * LOG2PI_F - ld);
        }
    }
}

// ---------------- bf16x3 HMMA GEMM, 128x128 block tile ----------------
#define PITCH 20
#define PLW   (128*PITCH)
#define STW   (4*PLW)
#define GSMEM (2*STW*4)

// CM: 0 = fp32 C row-major; 1 = packed planes Ph/Pl; 2 = KV scatter C[slice][m][64];
//     3 = fused out-layer atomics into C[row*3+v] (wout = out weights);
//     4 = planes output with rank-3 mu epilogue add (wout = W_mu rows [3][512], blk = flow block)
template <int ACT0, int ACT1, int CM>
__global__ void __launch_bounds__(256, 2)
k_mma(const unsigned* __restrict__ Ah0, const unsigned* __restrict__ Al0,
      const unsigned* __restrict__ Wh0, const unsigned* __restrict__ Wl0,
      const float* __restrict__ b0, float* __restrict__ C0,
      unsigned* __restrict__ Ph0, unsigned* __restrict__ Pl0,
      const unsigned* __restrict__ Ah1, const unsigned* __restrict__ Al1,
      const unsigned* __restrict__ Wh1, const unsigned* __restrict__ Wl1,
      const float* __restrict__ b1, float* __restrict__ C1,
      unsigned* __restrict__ Ph1, unsigned* __restrict__ Pl1,
      int M, int N, int KP2,
      const float* __restrict__ wout0, const float* __restrict__ wout1, int blk) {
    extern __shared__ __align__(16) unsigned dsm[];

    bool first = (blockIdx.z == 0);
    const unsigned* Ah = first ? Ah0 : Ah1;
    const unsigned* Al = first ? Al0 : Al1;
    const unsigned* Wh = first ? Wh0 : Wh1;
    const unsigned* Wl = first ? Wl0 : Wl1;
    const float* bias  = first ? b0 : b1;
    float* C           = first ? C0 : C1;
    unsigned* Ph       = first ? Ph0 : Ph1;
    unsigned* Pl       = first ? Pl0 : Pl1;
    const float* wout  = first ? wout0 : wout1;

    int tile_m = blockIdx.y * 128;
    int tile_n = blockIdx.x * 128;
    int tid = threadIdx.x, lane = tid & 31, wid = tid >> 5;
    int grp = lane >> 2, tig = lane & 3;
    int wm = wid & 3, wn = wid >> 2;
    unsigned sbb = (unsigned)__cvta_generic_to_shared(dsm);

    float acc[2][8][4];
#pragma unroll
    for (int i = 0; i < 2; i++)
#pragma unroll
        for (int j = 0; j < 8; j++)
#pragma unroll
            for (int e = 0; e < 4; e++) acc[i][j][e] = 0.f;

    auto load_stage = [&](int st, int kp0) {
        unsigned base = (unsigned)st * STW;
#pragma unroll
        for (int t = 0; t < 4; t++) {
            int idx = tid + t * 256;
            int p = idx >> 9, r = (idx >> 2) & 127, c = idx & 3;
            int gm = tile_m + r; if (gm >= M) gm = M - 1;
            const unsigned* src = (p ? Al : Ah) + (long)gm * KP2 + kp0 + c * 4;
            cpa16s(sbb + (base + (unsigned)p * PLW + (unsigned)(r * PITCH + c * 4)) * 4u, src);
        }
#pragma unroll
        for (int t = 0; t < 4; t++) {
            int idx = tid + t * 256;
            int p = idx >> 9, r = (idx >> 2) & 127, c = idx & 3;
            int gn = tile_n + r;
            const unsigned* src = (p ? Wl : Wh) + (long)gn * KP2 + kp0 + c * 4;
            cpa16s(sbb + (base + 2u * PLW + (unsigned)p * PLW + (unsigned)(r * PITCH + c * 4)) * 4u, src);
        }
        asm volatile("cp.async.commit_group;" ::: "memory");
    };

    int iters = KP2 / 16;
    load_stage(0, 0);

    for (int it = 0; it < iters; it++) {
        if (it + 1 < iters) {
            load_stage((it + 1) & 1, (it + 1) * 16);
            asm volatile("cp.async.wait_group 1;" ::: "memory");
        } else {
            asm volatile("cp.async.wait_group 0;" ::: "memory");
        }
        __syncthreads();

        unsigned base = (unsigned)(it & 1) * STW;
        const unsigned* SAh = dsm + base;
        const unsigned* SAl = dsm + base + PLW;
        const unsigned* SBh = dsm + base + 2 * PLW;
        const unsigned* SBl = dsm + base + 3 * PLW;

#pragma unroll
        for (int s2 = 0; s2 < 2; s2++) {
            int kb = s2 * 8;
            unsigned ah[2][4], al[2][4];
#pragma unroll
            for (int i = 0; i < 2; i++) {
                int rb = wm * 32 + i * 16 + grp;
                ah[i][0] = SAh[rb * PITCH + kb + tig];
                ah[i][1] = SAh[(rb + 8) * PITCH + kb + tig];
                ah[i][2] = SAh[rb * PITCH + kb + tig + 4];
                ah[i][3] = SAh[(rb + 8) * PITCH + kb + tig + 4];
                al[i][0] = SAl[rb * PITCH + kb + tig];
                al[i][1] = SAl[(rb + 8) * PITCH + kb + tig];
                al[i][2] = SAl[rb * PITCH + kb + tig + 4];
                al[i][3] = SAl[(rb + 8) * PITCH + kb + tig + 4];
            }
#pragma unroll
            for (int j = 0; j < 8; j++) {
                int nb = wn * 64 + j * 8 + grp;
                unsigned bh[2], bl[2];
                bh[0] = SBh[nb * PITCH + kb + tig];
                bh[1] = SBh[nb * PITCH + kb + tig + 4];
                bl[0] = SBl[nb * PITCH + kb + tig];
                bl[1] = SBl[nb * PITCH + kb + tig + 4];
#pragma unroll
                for (int i = 0; i < 2; i++) {
                    mma16(acc[i][j], ah[i], bh);
                    mma16(acc[i][j], al[i], bh);
                    mma16(acc[i][j], ah[i], bl);
                }
            }
        }
        __syncthreads();
    }

    int np2 = N >> 1;
    float part[2][2][3];
    if (CM == 3) {
#pragma unroll
        for (int i = 0; i < 2; i++)
#pragma unroll
            for (int rp = 0; rp < 2; rp++)
#pragma unroll
                for (int v = 0; v < 3; v++) part[i][rp][v] = 0.f;
    }
#pragma unroll
    for (int i = 0; i < 2; i++) {
        int row0 = tile_m + wm * 32 + i * 16 + grp;
        int row1 = row0 + 8;
        float mu0[3], mu1[3];
        if (CM == 4) {
            int r0 = (row0 < M) ? row0 : M - 1;
            int r1 = (row1 < M) ? row1 : M - 1;
#pragma unroll
            for (int v = 0; v < 3; v++) {
                float mk = ((v + blk) & 1) ? 1.f : 0.f;
                mu0[v] = mk * g_u[r0 * 3 + v];
                mu1[v] = mk * g_u[r1 * 3 + v];
            }
        }
#pragma unroll
        for (int j = 0; j < 8; j++) {
            int col = tile_n + wn * 64 + j * 8 + tig * 2;
            float b0v = bias[col], b1v = bias[col + 1];
            float v00 = acc[i][j][0] + b0v, v01 = acc[i][j][1] + b1v;
            float v10 = acc[i][j][2] + b0v, v11 = acc[i][j][3] + b1v;
            if (CM == 4) {
                float w00 = wout[col],        w01 = wout[col + 1];
                float w10 = wout[HDIM + col], w11 = wout[HDIM + col + 1];
                float w20 = wout[2*HDIM + col], w21 = wout[2*HDIM + col + 1];
                v00 += mu0[0]*w00 + mu0[1]*w10 + mu0[2]*w20;
                v01 += mu0[0]*w01 + mu0[1]*w11 + mu0[2]*w21;
                v10 += mu1[0]*w00 + mu1[1]*w10 + mu1[2]*w20;
                v11 += mu1[0]*w01 + mu1[1]*w11 + mu1[2]*w21;
            }
            if (first) {
                v00 = actf<ACT0>(v00); v01 = actf<ACT0>(v01);
                v10 = actf<ACT0>(v10); v11 = actf<ACT0>(v11);
            } else {
                v00 = actf<ACT1>(v00); v01 = actf<ACT1>(v01);
                v10 = actf<ACT1>(v10); v11 = actf<ACT1>(v11);
            }
            if (CM == 3) {
#pragma unroll
                for (int v = 0; v < 3; v++) {
                    float w0 = wout[col * 3 + v], w1 = wout[(col + 1) * 3 + v];
                    part[i][0][v] += v00 * w0 + v01 * w1;
                    part[i][1][v] += v10 * w0 + v11 * w1;
                }
            } else if (CM == 2) {
                int slice = col >> 6, cis = col & 63;
                float* d0 = C + ((long)slice * M + row0) * 64 + cis;
                float* d1 = C + ((long)slice * M + row1) * 64 + cis;
                if (row0 < M) { d0[0] = v00; d0[1] = v01; }
                if (row1 < M) { d1[0] = v10; d1[1] = v11; }
            } else if (CM == 0) {
                if (row0 < M) { C[(long)row0 * N + col] = v00; C[(long)row0 * N + col + 1] = v01; }
                if (row1 < M) { C[(long)row1 * N + col] = v10; C[(long)row1 * N + col + 1] = v11; }
            } else {
                unsigned lo, hi;
                if (row0 < M) {
                    hi = splitpack(v00, v01, lo);
                    Ph[(long)row0 * np2 + (col >> 1)] = hi;
                    Pl[(long)row0 * np2 + (col >> 1)] = lo;
                }
                if (row1 < M) {
                    hi = splitpack(v10, v11, lo);
                    Ph[(long)row1 * np2 + (col >> 1)] = hi;
                    Pl[(long)row1 * np2 + (col >> 1)] = lo;
                }
            }
        }
    }
    if (CM == 3) {
#pragma unroll
        for (int i = 0; i < 2; i++) {
            int row0 = tile_m + wm * 32 + i * 16 + grp;
            int row1 = row0 + 8;
#pragma unroll
            for (int v = 0; v < 3; v++) {
                if (row0 < M) atomicAdd(&C[row0 * 3 + v], part[i][0][v]);
                if (row1 < M) atomicAdd(&C[row1 * 3 + v], part[i][1][v]);
            }
        }
    }
}

// ---------------- attention ----------------
__global__ void k_attn2(const float* __restrict__ keys, const float* __restrict__ vals, int l) {
    int h = blockIdx.x & 7, b = blockIdx.x >> 3;
    int tid = threadIdx.x, lane = tid & 31, wq = tid >> 5;
    __shared__ float KsT[DD * TT];
    __shared__ float Vs[TT * DD];
    __shared__ float Qs[T2_ * DD];
    __shared__ float Ps[4][64];

    long base = ((long)(l * HH + h) * MKV + (long)b * TT) * DD;
    const float4* k4 = (const float4*)(keys + base);
    const float4* v4 = (const float4*)(vals + base);
    for (int i = tid; i < TT * DD / 4; i += 128) {
        float4 kv = k4[i];
        int w = i >> 4, d = (i & 15) << 2;
        KsT[(d + 0) * TT + w] = kv.x;
        KsT[(d + 1) * TT + w] = kv.y;
        KsT[(d + 2) * TT + w] = kv.z;
        KsT[(d + 3) * TT + w] = kv.w;
        ((float4*)Vs)[i] = v4[i];
    }
    for (int i = tid; i < T2_ * DD / 4; i += 128) {
        int q = i >> 4, d4 = (i & 15);
        ((float4*)Qs)[i] = *(const float4*)(g_attval + (long)(b * T2_ + q) * HDIM + h * DD + d4 * 4);
    }
    __syncthreads();

#pragma unroll
    for (int qi = 0; qi < 3; qi++) {
        int q = wq + qi * 4;
        int lim = (TT - T2_) + q;
        float d0 = 0.f, d1 = 0.f;
        const float* qrow = Qs + q * DD;
#pragma unroll
        for (int d = 0; d < DD; d++) {
            float qd = qrow[d];
            d0 += qd * KsT[d * TT + lane];
            d1 += qd * KsT[d * TT + ((lane + 32) & 63)];
        }
        float s0 = (lane < lim) ? d0 * 0.125f : -1e30f;
        float s1 = (lane + 32 < lim) ? d1 * 0.125f : -1e30f;
        float mx = fmaxf(s0, s1);
#pragma unroll
        for (int o = 16; o; o >>= 1) mx = fmaxf(mx, __shfl_xor_sync(0xffffffffu, mx, o));
        float e0 = (lane < lim) ? expf(s0 - mx) : 0.f;
        float e1 = (lane + 32 < lim) ? expf(s1 - mx) : 0.f;
        float sm = e0 + e1;
#pragma unroll
        for (int o = 16; o; o >>= 1) sm += __shfl_xor_sync(0xffffffffu, sm, o);
        Ps[wq][lane] = e0;
        Ps[wq][lane + 32] = e1;
        __syncwarp();
        float inv = 1.f / sm;
        float o0 = 0.f, o1 = 0.f;
        for (int w2 = 0; w2 < lim; w2++) {
            float p = Ps[wq][w2];
            o0 += p * Vs[w2 * DD + lane];
            o1 += p * Vs[w2 * DD + lane + 32];
        }
        long orow = (long)(b * T2_ + q) * HDIM + h * DD;
        g_att[orow + lane] = o0 * inv;
        g_att[orow + lane + 32] = o1 * inv;
        __syncwarp();
    }
}

// ---------------- add + layernorm: warp per row, shuffle reductions ----------------
__global__ void k_add_ln(float* __restrict__ x, const float* __restrict__ y,
                         const float* __restrict__ gamma, const float* __restrict__ beta) {
    int w = threadIdx.x >> 5, lane = threadIdx.x & 31;
    int m = blockIdx.x * 8 + w;
    long base = (long)m * HDIM;
    float4 xv[4];
#pragma unroll
    for (int k = 0; k < 4; k++) {
        int off = k * 128 + lane * 4;
        float4 a = *(const float4*)&x[base + off];
        float4 b = *(const float4*)&y[base + off];
        xv[k].x = a.x + b.x; xv[k].y = a.y + b.y;
        xv[k].z = a.z + b.z; xv[k].w = a.w + b.w;
    }
    float s = 0.f;
#pragma unroll
    for (int k = 0; k < 4; k++) s += xv[k].x + xv[k].y + xv[k].z + xv[k].w;
#pragma unroll
    for (int o = 16; o; o >>= 1) s += __shfl_xor_sync(0xffffffffu, s, o);
    float mean = s / (float)HDIM;
    float q = 0.f;
#pragma unroll
    for (int k = 0; k < 4; k++) {
        xv[k].x -= mean; xv[k].y -= mean; xv[k].z -= mean; xv[k].w -= mean;
        q += xv[k].x * xv[k].x + xv[k].y * xv[k].y + xv[k].z * xv[k].z + xv[k].w * xv[k].w;
    }
#pragma unroll
    for (int o = 16; o; o >>= 1) q += __shfl_xor_sync(0xffffffffu, q, o);
    float r = rsqrtf(q / (float)HDIM + 1e-5f);
#pragma unroll
    for (int k = 0; k < 4; k++) {
        int off = k * 128 + lane * 4;
        float4 g = *(const float4*)&gamma[off];
        float4 bb = *(const float4*)&beta[off];
        float4 o4;
        o4.x = xv[k].x * r * g.x + bb.x;
        o4.y = xv[k].y * r * g.y + bb.y;
        o4.z = xv[k].z * r * g.z + bb.z;
        o4.w = xv[k].w * r * g.w + bb.w;
        *(float4*)&x[base + off] = o4;
        unsigned lo0, hi0 = splitpack(o4.x, o4.y, lo0);
        unsigned lo1, hi1 = splitpack(o4.z, o4.w, lo1);
        long pb = (long)m * HKP + k * 64 + lane * 2;
        a_av_h[pb] = hi0; a_av_h[pb + 1] = hi1;
        a_av_l[pb] = lo0; a_av_l[pb + 1] = lo1;
    }
}

// ---------------- host ----------------
static inline int ceildiv(int a, int b) { return (a + b - 1) / b; }

extern "C" void kernel_launch(void* const* d_in, const int* in_sizes, int n_in,
                              void* d_out, int out_size) {
    const float* encoded   = (const float*)d_in[0];
    const float* true_val  = (const float*)d_in[1];
    const float* W_shift   = (const float*)d_in[2];
    const float* b_shift   = (const float*)d_in[3];
    const float* W_key     = (const float*)d_in[4];
    const float* b_key     = (const float*)d_in[5];
    const float* W_val     = (const float*)d_in[6];
    const float* b_val     = (const float*)d_in[7];
    const float* ln1_s     = (const float*)d_in[8];
    const float* ln1_b     = (const float*)d_in[9];
    const float* ff_w1     = (const float*)d_in[10];
    const float* ff_b1     = (const float*)d_in[11];
    const float* ff_w2     = (const float*)d_in[12];
    const float* ff_b2     = (const float*)d_in[13];
    const float* ln2_s     = (const float*)d_in[14];
    const float* ln2_b     = (const float*)d_in[15];
    const float* s_w_in    = (const float*)d_in[16];
    const float* s_b_in    = (const float*)d_in[17];
    const float* s_w_hid   = (const float*)d_in[18];
    const float* s_b_hid   = (const float*)d_in[19];
    const float* s_w_out   = (const float*)d_in[20];
    const float* s_b_out   = (const float*)d_in[21];
    const float* t_w_in    = (const float*)d_in[22];
    const float* t_b_in    = (const float*)d_in[23];
    const float* t_w_hid   = (const float*)d_in[24];
    const float* t_b_hid   = (const float*)d_in[25];
    const float* t_w_out   = (const float*)d_in[26];
    const float* t_b_out   = (const float*)d_in[27];
    const float* bn_lg     = (const float*)d_in[28];
    const float* bn_bt     = (const float*)d_in[29];

    float *keys, *vals, *attval, *att, *sbuf, *tbuf;
    unsigned *evh, *evl, *aih, *ail, *avh, *avl;
    unsigned *h1h, *h1l, *h2h, *h2l, *h3h, *h3l, *h4h, *h4l;
    unsigned *wshh, *wshl, *wf1h, *wf1l, *wf2h, *wf2l, *winh, *winl, *whdh, *whdl, *wkvh, *wkvl;
    cudaGetSymbolAddress((void**)&keys,   g_keys);
    cudaGetSymbolAddress((void**)&vals,   g_vals);
    cudaGetSymbolAddress((void**)&attval, g_attval);
    cudaGetSymbolAddress((void**)&att,    g_att);
    cudaGetSymbolAddress((void**)&sbuf,   g_s);
    cudaGetSymbolAddress((void**)&tbuf,   g_t);
    cudaGetSymbolAddress((void**)&evh, a_ev_h);  cudaGetSymbolAddress((void**)&evl, a_ev_l);
    cudaGetSymbolAddress((void**)&aih, a_ai_h);  cudaGetSymbolAddress((void**)&ail, a_ai_l);
    cudaGetSymbolAddress((void**)&avh, a_av_h);  cudaGetSymbolAddress((void**)&avl, a_av_l);
    cudaGetSymbolAddress((void**)&h1h, a_h1h);   cudaGetSymbolAddress((void**)&h1l, a_h1l);
    cudaGetSymbolAddress((void**)&h2h, a_h2h);   cudaGetSymbolAddress((void**)&h2l, a_h2l);
    cudaGetSymbolAddress((void**)&h3h, a_h3h);   cudaGetSymbolAddress((void**)&h3l, a_h3l);
    cudaGetSymbolAddress((void**)&h4h, a_h4h);   cudaGetSymbolAddress((void**)&h4l, a_h4l);
    cudaGetSymbolAddress((void**)&wshh, w_shT_h); cudaGetSymbolAddress((void**)&wshl, w_shT_l);
    cudaGetSymbolAddress((void**)&wf1h, w_f1T_h); cudaGetSymbolAddress((void**)&wf1l, w_f1T_l);
    cudaGetSymbolAddress((void**)&wf2h, w_f2T_h); cudaGetSymbolAddress((void**)&wf2l, w_f2T_l);
    cudaGetSymbolAddress((void**)&winh, w_inT_h); cudaGetSymbolAddress((void**)&winl, w_inT_l);
    cudaGetSymbolAddress((void**)&whdh, w_hdT_h); cudaGetSymbolAddress((void**)&whdl, w_hdT_l);
    cudaGetSymbolAddress((void**)&wkvh, w_kvT_h); cudaGetSymbolAddress((void**)&wkvl, w_kvT_l);

    cudaFuncSetAttribute(k_mma<0,0,0>, cudaFuncAttributeMaxDynamicSharedMemorySize, GSMEM);
    cudaFuncSetAttribute(k_mma<0,0,2>, cudaFuncAttributeMaxDynamicSharedMemorySize, GSMEM);
    cudaFuncSetAttribute(k_mma<1,1,1>, cudaFuncAttributeMaxDynamicSharedMemorySize, GSMEM);
    cudaFuncSetAttribute(k_mma<2,2,1>, cudaFuncAttributeMaxDynamicSharedMemorySize, GSMEM);
    cudaFuncSetAttribute(k_mma<1,1,3>, cudaFuncAttributeMaxDynamicSharedMemorySize, GSMEM);
    cudaFuncSetAttribute(k_mma<2,2,3>, cudaFuncAttributeMaxDynamicSharedMemorySize, GSMEM);
    cudaFuncSetAttribute(k_mma<1,1,4>, cudaFuncAttributeMaxDynamicSharedMemorySize, GSMEM);
    cudaFuncSetAttribute(k_mma<2,2,4>, cudaFuncAttributeMaxDynamicSharedMemorySize, GSMEM);

    cudaStream_t s2;
    cudaStreamCreateWithFlags(&s2, cudaStreamNonBlocking);
    cudaEvent_t evF, evT;
    cudaEventCreateWithFlags(&evF, cudaEventDisableTiming);
    cudaEventCreateWithFlags(&evT, cudaEventDisableTiming);

    long kvoff = (long)NKV * EVKP;
    long inoff = (long)NB_ * HDIM * HKP;
    long hdoff = (long)NB_ * NHID_ * HDIM * HKP;
    long instride = (long)(HDIM + VV) * HDIM;

    // ---- serial prologue: KV convs + builders, KV GEMM at launch #5 ----
    k_convwT<<<dim3(ceildiv(DD*EVKP,256),1,LLAY*HH), 256>>>(W_key, wkvh, wkvl, DIN_, DD, EVKP, (long)DIN_*DD);   // 0
    k_convwT<<<dim3(ceildiv(DD*EVKP,256),1,LLAY*HH), 256>>>(W_val, wkvh+kvoff, wkvl+kvoff, DIN_, DD, EVKP, (long)DIN_*DD); // 1
    k_build_ev<<<(int)(((long)MKV*EVKP + 255)/256), 256>>>(encoded, true_val);                                   // 2
    k_build_attin<<<(int)(((long)MQ*AIKP + 255)/256), 256>>>(encoded);                                           // 3
    k_init_u<<<ceildiv(MQ, 256), 256>>>(true_val, (float*)d_out);                                                // 4

    {
        dim3 g(NKV/128, ceildiv(MKV, 128), 2);
        k_mma<0,0,2><<<g, 256, GSMEM>>>(evh, evl, wkvh, wkvl, b_key, keys, 0, 0,
                                        evh, evl, wkvh+kvoff, wkvl+kvoff, b_val, vals, 0, 0,
                                        MKV, NKV, EVKP, 0, 0, 0);                                                // 5
    }

    // ---- remaining weight conversions (serial) ----
    k_convwT<<<dim3(ceildiv(HDIM*AIKP,256),1,1), 256>>>(W_shift, wshh, wshl, VV*CC, HDIM, AIKP, (long)VV*CC*HDIM);
    k_convwT<<<dim3(ceildiv(HDIM*HKP,256),1,LLAY), 256>>>(ff_w1, wf1h, wf1l, HDIM, HDIM, HKP, (long)HDIM*HDIM);
    k_convwT<<<dim3(ceildiv(HDIM*HKP,256),1,LLAY), 256>>>(ff_w2, wf2h, wf2l, HDIM, HDIM, HKP, (long)HDIM*HDIM);
    k_convwT<<<dim3(ceildiv(HDIM*HKP,256),1,NB_), 256>>>(s_w_in, winh, winl, HDIM, HDIM, HKP, instride);
    k_convwT<<<dim3(ceildiv(HDIM*HKP,256),1,NB_), 256>>>(t_w_in, winh+inoff, winl+inoff, HDIM, HDIM, HKP, instride);
    k_convwT<<<dim3(ceildiv(HDIM*HKP,256),1,NB_*NHID_), 256>>>(s_w_hid, whdh, whdl, HDIM, HDIM, HKP, (long)HDIM*HDIM);
    k_convwT<<<dim3(ceildiv(HDIM*HKP,256),1,NB_*NHID_), 256>>>(t_w_hid, whdh+hdoff, whdl+hdoff, HDIM, HDIM, HKP, (long)HDIM*HDIM);

    // ---- shift ----
    {
        dim3 g(HDIM/128, ceildiv(MQ, 128), 1);
        k_mma<0,0,0><<<g, 256, GSMEM>>>(aih, ail, wshh, wshl, b_shift, attval, 0, 0,
                                        aih, ail, wshh, wshl, b_shift, attval, 0, 0,
                                        MQ, HDIM, AIKP, 0, 0, 0);
    }

    // ---- transformer layers ----
    for (int l = 0; l < LLAY; l++) {
        k_attn2<<<BNN*HH, 128>>>(keys, vals, l);
        k_add_ln<<<MQ/8, 256>>>(attval, att, ln1_s + (long)l*HDIM, ln1_b + (long)l*HDIM);
        dim3 g(HDIM/128, ceildiv(MQ, 128), 1);
        k_mma<1,1,1><<<g, 256, GSMEM>>>(avh, avl, wf1h + (long)l*HDIM*HKP, wf1l + (long)l*HDIM*HKP,
                                        ff_b1 + (long)l*HDIM, 0, h1h, h1l,
                                        avh, avl, wf1h + (long)l*HDIM*HKP, wf1l + (long)l*HDIM*HKP,
                                        ff_b1 + (long)l*HDIM, 0, h1h, h1l,
                                        MQ, HDIM, HKP, 0, 0, 0);
        k_mma<0,0,0><<<g, 256, GSMEM>>>(h1h, h1l, wf2h + (long)l*HDIM*HKP, wf2l + (long)l*HDIM*HKP,
                                        ff_b2 + (long)l*HDIM, att, 0, 0,
                                        h1h, h1l, wf2h + (long)l*HDIM*HKP, wf2l + (long)l*HDIM*HKP,
                                        ff_b2 + (long)l*HDIM, att, 0, 0,
                                        MQ, HDIM, HKP, 0, 0, 0);
        k_add_ln<<<MQ/8, 256>>>(attval, att, ln2_s + (long)l*HDIM, ln2_b + (long)l*HDIM);
    }

    // ---- RealNVP flow ----
    dim3 gs(HDIM/128, ceildiv(MQ, 128), 1);

    for (int blk = 0; blk < NB_; blk++) {
        cudaEventRecord(evF, 0);
        cudaStreamWaitEvent(s2, evF, 0);

        const float* smuw = s_w_in + (long)blk * instride + (long)HDIM * HDIM;
        const float* tmuw = t_w_in + (long)blk * instride + (long)HDIM * HDIM;

        k_mma<2,2,4><<<gs, 256, GSMEM>>>(avh, avl, winh + (long)blk*HDIM*HKP, winl + (long)blk*HDIM*HKP,
                                         s_b_in + (long)blk*HDIM, 0, h1h, h1l,
                                         avh, avl, winh + (long)blk*HDIM*HKP, winl + (long)blk*HDIM*HKP,
                                         s_b_in + (long)blk*HDIM, 0, h1h, h1l,
                                         MQ, HDIM, HKP, smuw, smuw, blk);
        k_mma<1,1,4><<<gs, 256, GSMEM, s2>>>(avh, avl, winh + inoff + (long)blk*HDIM*HKP, winl + inoff + (long)blk*HDIM*HKP,
                                             t_b_in + (long)blk*HDIM, 0, h3h, h3l,
                                             avh, avl, winh + inoff + (long)blk*HDIM*HKP, winl + inoff + (long)blk*HDIM*HKP,
                                             t_b_in + (long)blk*HDIM, 0, h3h, h3l,
                                             MQ, HDIM, HKP, tmuw, tmuw, blk);

        unsigned *csh = h1h, *csl = h1l, *nsh = h2h, *nsl = h2l;
        unsigned *cth = h3h, *ctl = h3l, *nth = h4h, *ntl = h4l;
        for (int i = 0; i < NHID_ - 1; i++) {
            long wo = ((long)blk*NHID_ + i)*HDIM*HKP;
            k_mma<2,2,1><<<gs, 256, GSMEM>>>(csh, csl, whdh + wo, whdl + wo,
                                             s_b_hid + ((long)blk*NHID_ + i)*HDIM, 0, nsh, nsl,
                                             csh, csl, whdh + wo, whdl + wo,
                                             s_b_hid + ((long)blk*NHID_ + i)*HDIM, 0, nsh, nsl,
                                             MQ, HDIM, HKP, 0, 0, 0);
            k_mma<1,1,1><<<gs, 256, GSMEM, s2>>>(cth, ctl, whdh + hdoff + wo, whdl + hdoff + wo,
                                                 t_b_hid + ((long)blk*NHID_ + i)*HDIM, 0, nth, ntl,
                                                 cth, ctl, whdh + hdoff + wo, whdl + hdoff + wo,
                                                 t_b_hid + ((long)blk*NHID_ + i)*HDIM, 0, nth, ntl,
                                                 MQ, HDIM, HKP, 0, 0, 0);
            unsigned* t;
            t = csh; csh = nsh; nsh = t;  t = csl; csl = nsl; nsl = t;
            t = cth; cth = nth; nth = t;  t = ctl; ctl = ntl; ntl = t;
        }
        {
            int i = NHID_ - 1;
            long wo = ((long)blk*NHID_ + i)*HDIM*HKP;
            k_mma<2,2,3><<<gs, 256, GSMEM>>>(csh, csl, whdh + wo, whdl + wo,
                                             s_b_hid + ((long)blk*NHID_ + i)*HDIM, sbuf, 0, 0,
                                             csh, csl, whdh + wo, whdl + wo,
                                             s_b_hid + ((long)blk*NHID_ + i)*HDIM, sbuf, 0, 0,
                                             MQ, HDIM, HKP,
                                             s_w_out + (long)blk*HDIM*VV, s_w_out + (long)blk*HDIM*VV, 0);
            k_mma<1,1,3><<<gs, 256, GSMEM, s2>>>(cth, ctl, whdh + hdoff + wo, whdl + hdoff + wo,
                                                 t_b_hid + ((long)blk*NHID_ + i)*HDIM, tbuf, 0, 0,
                                                 cth, ctl, whdh + hdoff + wo, whdl + hdoff + wo,
                                                 t_b_hid + ((long)blk*NHID_ + i)*HDIM, tbuf, 0, 0,
                                                 MQ, HDIM, HKP,
                                                 t_w_out + (long)blk*HDIM*VV, t_w_out + (long)blk*HDIM*VV, 0);
        }

        cudaEventRecord(evT, s2);
        cudaStreamWaitEvent(0, evT, 0);

        k_cpl_bn<<<T2_*VV, 256>>>(s_b_out + (long)blk*VV, t_b_out + (long)blk*VV,
                                  bn_lg + (long)blk*VV, bn_bt + (long)blk*VV,
                                  (float*)d_out, blk);
    }
}